// round 8
// baseline (speedup 1.0000x reference)
#include <cuda_runtime.h>
#include <cstddef>

// GloVe loss — counting-sort bucketing by c>>7 (3 aux launches), with the
// exact in-bucket sort (by c&127) FUSED into the main kernel: each main block
// owns one bucket, sorts its ~335 records in shared memory (overlapped with
// other blocks' gather traffic), then 8 warps walk sorted chunks with
// register-held center-row reuse.

static constexpr int EMB           = 300;
static constexpr int NV4           = EMB / 4;       // 75 float4 per row
static constexpr int BATCH_N       = 262144;

static constexpr int BUCKET_SHIFT  = 7;
static constexpr int NB            = 1024;          // covers 100000>>7 = 782
static constexpr int NB_USED       = 782;
static constexpr int SORT_CAP      = 768;           // avg bucket 335, sd ~18

static constexpr int STHREADS      = 512;
static constexpr int SCHUNK        = 2048;
static constexpr int SBLOCKS      = BATCH_N / SCHUNK;   // 128
static constexpr int SPT           = SCHUNK / STHREADS;  // 4

static constexpr int THREADS       = 256;
static constexpr int WARPS_PER_BLK = THREADS / 32;  // 8

// Replay-safe: g_cnt zeroed by scan after read; g_base fully rewritten by
// scan; s_recs fully overwritten; g_acc/g_done reset by last main block.
__device__ int    g_cnt[NB];
__device__ int    g_base[NB];
__device__ int4   s_recs[BATCH_N];
__device__ double g_acc;
__device__ unsigned int g_done;

// ---- 1) histogram by c>>7 ---------------------------------------------------
__global__ __launch_bounds__(STHREADS) void glove_hist_kernel(
    const int* __restrict__ center)
{
    __shared__ int h[NB];
    const int tid  = threadIdx.x;
    const int idx0 = blockIdx.x * SCHUNK;
    for (int i = tid; i < NB; i += STHREADS) h[i] = 0;
    __syncthreads();
    #pragma unroll
    for (int k = 0; k < SPT; ++k) {
        const int c = __ldg(center + idx0 + k * STHREADS + tid);
        atomicAdd(&h[c >> BUCKET_SHIFT], 1);
    }
    __syncthreads();
    for (int b = tid; b < NB; b += STHREADS)
        if (h[b]) atomicAdd(&g_cnt[b], h[b]);
}

// ---- 2) exclusive scan; re-zero counts for replay ---------------------------
__global__ __launch_bounds__(NB) void glove_scan_kernel()
{
    __shared__ int tmp[NB];
    const int t = threadIdx.x;
    const int v = g_cnt[t];
    g_cnt[t] = 0;
    tmp[t] = v;
    __syncthreads();
    #pragma unroll
    for (int off = 1; off < NB; off <<= 1) {
        int u = (t >= off) ? tmp[t - off] : 0;
        __syncthreads();
        tmp[t] += u;
        __syncthreads();
    }
    g_base[t] = tmp[t] - v;
}

// ---- 3) bucketed scatter ----------------------------------------------------
// After this kernel, g_base[b] == END offset of bucket b.
__global__ __launch_bounds__(STHREADS) void glove_scatter_kernel(
    const int*   __restrict__ center,
    const int*   __restrict__ outside,
    const float* __restrict__ coocs,
    const float* __restrict__ weighting)
{
    __shared__ int h[NB];
    __shared__ int base[NB];
    const int tid  = threadIdx.x;
    const int idx0 = blockIdx.x * SCHUNK;

    for (int i = tid; i < NB; i += STHREADS) h[i] = 0;
    __syncthreads();

    int c[SPT];
    #pragma unroll
    for (int k = 0; k < SPT; ++k) {
        c[k] = __ldg(center + idx0 + k * STHREADS + tid);
        atomicAdd(&h[c[k] >> BUCKET_SHIFT], 1);
    }
    __syncthreads();
    for (int b = tid; b < NB; b += STHREADS) {
        const int n = h[b];
        base[b] = n ? atomicAdd(&g_base[b], n) : 0;
    }
    __syncthreads();
    for (int i = tid; i < NB; i += STHREADS) h[i] = 0;   // reuse as cursors
    __syncthreads();

    #pragma unroll
    for (int k = 0; k < SPT; ++k) {
        const int i = idx0 + k * STHREADS + tid;
        const int b = c[k] >> BUCKET_SHIFT;
        const int off = atomicAdd(&h[b], 1);
        int4 rec;
        rec.x = c[k];
        rec.y = __ldg(outside + i);
        rec.z = __float_as_int(__ldg(coocs + i));
        rec.w = __float_as_int(__ldg(weighting + i));
        s_recs[base[b] + off] = rec;
    }
}

// ---- 4) main: in-smem exact sort + gather with center-row reuse -------------
__global__ __launch_bounds__(THREADS, 6) void glove_main_kernel(
    const float* __restrict__ cemb,
    const float* __restrict__ oemb,
    const float* __restrict__ cbias,
    const float* __restrict__ obias,
    float*       __restrict__ out)
{
    __shared__ int4 raw [SORT_CAP];
    __shared__ int4 srt [SORT_CAP];
    __shared__ int  cnt[128];
    __shared__ int  pos[128];
    __shared__ float sh[WARPS_PER_BLK];

    const int b    = blockIdx.x;
    const int tid  = threadIdx.x;
    const int lane = tid & 31;
    const int warp = tid >> 5;

    const int s = (b == 0) ? 0 : g_base[b - 1];
    const int n = g_base[b] - s;

    // ---- in-smem counting sort of this bucket by c&127 ----
    if (tid < 128) { cnt[tid] = 0; }
    __syncthreads();
    const bool fit = (n <= SORT_CAP);
    if (fit) {
        for (int i = tid; i < n; i += THREADS) {
            const int4 r = __ldg(&s_recs[s + i]);
            raw[i] = r;
            atomicAdd(&cnt[r.x & 127], 1);
        }
        __syncthreads();
        if (tid < 128) pos[tid] = cnt[tid];
        __syncthreads();
        #pragma unroll
        for (int off = 1; off < 128; off <<= 1) {
            int u = (tid < 128 && tid >= off) ? pos[tid - off] : 0;
            __syncthreads();
            if (tid < 128) pos[tid] += u;
            __syncthreads();
        }
        if (tid < 128) pos[tid] -= cnt[tid];   // exclusive prefix = cursor
        __syncthreads();
        for (int i = tid; i < n; i += THREADS) {
            const int4 r = raw[i];
            srt[atomicAdd(&pos[r.x & 127], 1)] = r;
        }
        __syncthreads();
    }

    // ---- gather: each warp walks a contiguous sorted chunk ----
    const float4* __restrict__ cemb4 = reinterpret_cast<const float4*>(cemb);
    const float4* __restrict__ oemb4 = reinterpret_cast<const float4*>(oemb);

    const int chunk = (n + WARPS_PER_BLK - 1) / WARPS_PER_BLK;
    const int i0    = warp * chunk;
    const int i1    = (i0 + chunk < n) ? (i0 + chunk) : n;

    float wsum = 0.0f;
    int   prev = -1;
    float4 a0, a1, a2;
    float  cb = 0.0f;
    a0 = a1 = a2 = make_float4(0.f, 0.f, 0.f, 0.f);

    for (int i = i0; i < i1; ++i) {
        const int4 rec = fit ? srt[i] : __ldg(&s_recs[s + i]);

        const unsigned oo = (unsigned)rec.y * (unsigned)NV4 + (unsigned)lane;
        float4 b0 = __ldg(oemb4 + oo);
        float4 b1 = __ldg(oemb4 + oo + 32);
        float4 b2 = make_float4(0.f, 0.f, 0.f, 0.f);
        if (lane < NV4 - 64) b2 = __ldg(oemb4 + oo + 64);
        const float obv = __ldg(obias + rec.y);

        if (rec.x != prev) {   // warp-uniform (sorted)
            const unsigned co = (unsigned)rec.x * (unsigned)NV4 + (unsigned)lane;
            a0 = __ldg(cemb4 + co);
            a1 = __ldg(cemb4 + co + 32);
            a2 = make_float4(0.f, 0.f, 0.f, 0.f);
            if (lane < NV4 - 64) a2 = __ldg(cemb4 + co + 64);
            cb = __ldg(cbias + rec.x);
            prev = rec.x;
        }

        float dot = a0.x * b0.x + a0.y * b0.y + a0.z * b0.z + a0.w * b0.w;
        dot      += a1.x * b1.x + a1.y * b1.y + a1.z * b1.z + a1.w * b1.w;
        dot      += a2.x * b2.x + a2.y * b2.y + a2.z * b2.z + a2.w * b2.w;

        #pragma unroll
        for (int off = 16; off; off >>= 1)
            dot += __shfl_xor_sync(0xffffffffu, dot, off);

        if (lane == 0) {
            const float err = dot + cb + obv - __int_as_float(rec.z);
            wsum += __int_as_float(rec.w) * err * err;
        }
    }

    if (lane == 0) sh[warp] = wsum;
    __syncthreads();

    if (tid == 0) {
        float sblk = 0.0f;
        #pragma unroll
        for (int i = 0; i < WARPS_PER_BLK; ++i) sblk += sh[i];
        atomicAdd(&g_acc, (double)sblk);

        __threadfence();
        const unsigned t = atomicAdd(&g_done, 1u);
        if (t == (unsigned)(NB_USED - 1)) {
            const double v = atomicAdd(&g_acc, 0.0);
            out[0] = (float)v;
            g_acc  = 0.0;
            g_done = 0u;
        }
    }
}

extern "C" void kernel_launch(void* const* d_in, const int* in_sizes, int n_in,
                              void* d_out, int out_size) {
    const int*   center    = (const int*)  d_in[0];
    const int*   outside   = (const int*)  d_in[1];
    const float* coocs     = (const float*)d_in[2];
    const float* weighting = (const float*)d_in[3];
    const float* cemb      = (const float*)d_in[4];
    const float* oemb      = (const float*)d_in[5];
    const float* cbias     = (const float*)d_in[6];
    const float* obias     = (const float*)d_in[7];
    float* out = (float*)d_out;

    glove_hist_kernel<<<SBLOCKS, STHREADS>>>(center);
    glove_scan_kernel<<<1, NB>>>();
    glove_scatter_kernel<<<SBLOCKS, STHREADS>>>(center, outside, coocs, weighting);
    glove_main_kernel<<<NB_USED, THREADS>>>(cemb, oemb, cbias, obias, out);
}

// round 9
// speedup vs baseline: 1.0034x; 1.0034x over previous
#include <cuda_runtime.h>
#include <cstddef>

// GloVe loss — EXACT one-level counting sort by center index (100k buckets,
// spread global atomics) + R7-proven main gather with register-held
// center-row reuse. Launches: hist -> scan1 -> scan2 -> scatter -> main.

static constexpr int EMB           = 300;
static constexpr int NV4           = EMB / 4;       // 75 float4 per row
static constexpr int BATCH_N       = 262144;
static constexpr int VOC           = 100000;

static constexpr int SEG           = 1024;          // scan segment size
static constexpr int NSEG          = 98;            // 98*1024 = 100352 >= VOC
static constexpr int PAD           = NSEG * SEG;    // padded counter table

static constexpr int THREADS       = 256;
static constexpr int WARPS_PER_BLK = THREADS / 32;  // 8
static constexpr int ROWS_PER_WARP = 8;
static constexpr int MBLOCKS       = BATCH_N / (WARPS_PER_BLK * ROWS_PER_WARP); // 4096

// Replay-safe: g_cnt zeroed by scan1 after read; g_base/g_bsum/g_boff fully
// rewritten each launch; s_recs fully overwritten; g_acc/g_done reset by the
// last main block.
__device__ int    g_cnt[PAD];
__device__ int    g_base[PAD];
__device__ int    g_bsum[NSEG];
__device__ int    g_boff[NSEG];
__device__ int4   s_recs[BATCH_N];
__device__ double g_acc;
__device__ unsigned int g_done;

// ---- 1) per-center histogram (spread global atomics) ------------------------
__global__ __launch_bounds__(256) void glove_hist_kernel(
    const int* __restrict__ center)
{
    const int i = blockIdx.x * 256 + threadIdx.x;
    atomicAdd(&g_cnt[__ldg(center + i)], 1);
}

// ---- 2a) per-segment exclusive scan; zero counts; emit segment sums ---------
__global__ __launch_bounds__(SEG) void glove_scan1_kernel()
{
    __shared__ int tmp[SEG];
    const int t   = threadIdx.x;
    const int gid = blockIdx.x * SEG + t;
    const int v   = g_cnt[gid];
    g_cnt[gid] = 0;                      // restore for next replay
    tmp[t] = v;
    __syncthreads();
    #pragma unroll
    for (int off = 1; off < SEG; off <<= 1) {
        int u = (t >= off) ? tmp[t - off] : 0;
        __syncthreads();
        tmp[t] += u;
        __syncthreads();
    }
    g_base[gid] = tmp[t] - v;            // exclusive prefix within segment
    if (t == SEG - 1) g_bsum[blockIdx.x] = tmp[t];
}

// ---- 2b) scan of segment sums (tiny) ----------------------------------------
__global__ __launch_bounds__(128) void glove_scan2_kernel()
{
    __shared__ int tmp[128];
    const int t = threadIdx.x;
    const int v = (t < NSEG) ? g_bsum[t] : 0;
    tmp[t] = v;
    __syncthreads();
    #pragma unroll
    for (int off = 1; off < 128; off <<= 1) {
        int u = (t >= off) ? tmp[t - off] : 0;
        __syncthreads();
        tmp[t] += u;
        __syncthreads();
    }
    if (t < NSEG) g_boff[t] = tmp[t] - v;  // exclusive prefix of segments
}

// ---- 3) scatter into exactly-sorted positions -------------------------------
__global__ __launch_bounds__(256) void glove_scatter_kernel(
    const int*   __restrict__ center,
    const int*   __restrict__ outside,
    const float* __restrict__ coocs,
    const float* __restrict__ weighting)
{
    const int i = blockIdx.x * 256 + threadIdx.x;
    const int c = __ldg(center + i);
    int4 rec;
    rec.x = c;
    rec.y = __ldg(outside + i);
    rec.z = __float_as_int(__ldg(coocs + i));
    rec.w = __float_as_int(__ldg(weighting + i));
    const int pos = __ldg(&g_boff[c >> 10]) + atomicAdd(&g_base[c], 1);
    s_recs[pos] = rec;
}

// ---- 4) main gather with center-row register reuse (R7-proven) --------------
__global__ __launch_bounds__(THREADS, 6) void glove_main_kernel(
    const float* __restrict__ cemb,
    const float* __restrict__ oemb,
    const float* __restrict__ cbias,
    const float* __restrict__ obias,
    float*       __restrict__ out)
{
    const int lane  = threadIdx.x & 31;
    const int warp  = threadIdx.x >> 5;
    const int gwarp = blockIdx.x * WARPS_PER_BLK + warp;

    const float4* __restrict__ cemb4 = reinterpret_cast<const float4*>(cemb);
    const float4* __restrict__ oemb4 = reinterpret_cast<const float4*>(oemb);

    float wsum = 0.0f;
    int   prev = -1;
    float4 a0, a1, a2;
    float  cb = 0.0f;
    a0 = a1 = a2 = make_float4(0.f, 0.f, 0.f, 0.f);

    #pragma unroll 1
    for (int r = 0; r < ROWS_PER_WARP; ++r) {
        const int row = gwarp * ROWS_PER_WARP + r;
        const int4 rec = __ldg(&s_recs[row]);

        const unsigned oo = (unsigned)rec.y * (unsigned)NV4 + (unsigned)lane;
        float4 b0 = __ldg(oemb4 + oo);
        float4 b1 = __ldg(oemb4 + oo + 32);
        float4 b2 = make_float4(0.f, 0.f, 0.f, 0.f);
        if (lane < NV4 - 64) b2 = __ldg(oemb4 + oo + 64);
        const float obv = __ldg(obias + rec.y);

        if (rec.x != prev) {   // warp-uniform branch (records sorted by center)
            const unsigned co = (unsigned)rec.x * (unsigned)NV4 + (unsigned)lane;
            a0 = __ldg(cemb4 + co);
            a1 = __ldg(cemb4 + co + 32);
            a2 = make_float4(0.f, 0.f, 0.f, 0.f);
            if (lane < NV4 - 64) a2 = __ldg(cemb4 + co + 64);
            cb = __ldg(cbias + rec.x);
            prev = rec.x;
        }

        float dot = a0.x * b0.x + a0.y * b0.y + a0.z * b0.z + a0.w * b0.w;
        dot      += a1.x * b1.x + a1.y * b1.y + a1.z * b1.z + a1.w * b1.w;
        dot      += a2.x * b2.x + a2.y * b2.y + a2.z * b2.z + a2.w * b2.w;

        #pragma unroll
        for (int off = 16; off; off >>= 1)
            dot += __shfl_xor_sync(0xffffffffu, dot, off);

        if (lane == 0) {
            const float err = dot + cb + obv - __int_as_float(rec.z);
            wsum += __int_as_float(rec.w) * err * err;
        }
    }

    __shared__ float sh[WARPS_PER_BLK];
    if (lane == 0) sh[warp] = wsum;
    __syncthreads();

    if (threadIdx.x == 0) {
        float s = 0.0f;
        #pragma unroll
        for (int i = 0; i < WARPS_PER_BLK; ++i) s += sh[i];
        atomicAdd(&g_acc, (double)s);

        __threadfence();
        const unsigned t = atomicAdd(&g_done, 1u);
        if (t == (unsigned)(MBLOCKS - 1)) {
            const double v = atomicAdd(&g_acc, 0.0);
            out[0] = (float)v;
            g_acc  = 0.0;
            g_done = 0u;
        }
    }
}

extern "C" void kernel_launch(void* const* d_in, const int* in_sizes, int n_in,
                              void* d_out, int out_size) {
    const int*   center    = (const int*)  d_in[0];
    const int*   outside   = (const int*)  d_in[1];
    const float* coocs     = (const float*)d_in[2];
    const float* weighting = (const float*)d_in[3];
    const float* cemb      = (const float*)d_in[4];
    const float* oemb      = (const float*)d_in[5];
    const float* cbias     = (const float*)d_in[6];
    const float* obias     = (const float*)d_in[7];
    float* out = (float*)d_out;

    glove_hist_kernel<<<BATCH_N / 256, 256>>>(center);
    glove_scan1_kernel<<<NSEG, SEG>>>();
    glove_scan2_kernel<<<1, 128>>>();
    glove_scatter_kernel<<<BATCH_N / 256, 256>>>(center, outside, coocs, weighting);
    glove_main_kernel<<<MBLOCKS, THREADS>>>(cemb, oemb, cbias, obias, out);
}